// round 1
// baseline (speedup 1.0000x reference)
#include <cuda_runtime.h>
#include <cuda_fp16.h>
#include <stdint.h>

// ---------------------------------------------------------------------------
// DecoderStackLSTM: persistent-kernel 2-layer input-feed LSTM decoder.
// S=128 steps, B=64 batch, E=512 emb, H=1024 hidden.
// One persistent kernel (128 CTAs), grid barrier between layer phases.
// GEMMs via mma.sync.m16n8k16 (fp16 in, fp32 accum), weights converted to
// fp16 by prep kernels each launch (deterministic, graph-capturable).
// ---------------------------------------------------------------------------

#define S_   128
#define B_   64
#define E_   512
#define H_   1024
#define NJ   8                 // hidden columns per CTA
#define NR   32                // 4 gates * NJ weight rows per CTA
#define GRID (H_ / NJ)         // 128 CTAs
#define NTH  256
#define KC   64                // K chunk
#define KP   72                // padded smem row length in halves (144B)

static __device__ __align__(16) __half dWi0[4096 * 1536];
static __device__ __align__(16) __half dWh0[4096 * 1024];
static __device__ __align__(16) __half dWi1[4096 * 1024];
static __device__ __align__(16) __half dWh1[4096 * 1024];
static __device__ __align__(16) __half dEmb[S_ * B_ * E_];
static __device__ __align__(16) __half dH0[2][B_ * H_];
static __device__ __align__(16) __half dH1[2][B_ * H_];
static __device__ __align__(16) __half dOut0[B_ * H_];
static __device__ float dC0[B_ * H_];
static __device__ float dC1[B_ * H_];
static __device__ float dBs0[4 * H_];
static __device__ float dBs1[4 * H_];
static __device__ int   g_count;   // zero-init; reset to 0 at end of each run

// ---------------------------------------------------------------------------
// Prep kernels (run every launch; deterministic)
// ---------------------------------------------------------------------------

__global__ void prep_weights(const float* __restrict__ Wi0, const float* __restrict__ Wh0,
                             const float* __restrict__ Wi1, const float* __restrict__ Wh1,
                             const float* __restrict__ bi0, const float* __restrict__ bh0,
                             const float* __restrict__ bi1, const float* __restrict__ bh1) {
    const long total = 6291456L + 4194304L * 3;   // 18874368
    long stride = (long)gridDim.x * blockDim.x;
    long t0 = (long)blockIdx.x * blockDim.x + threadIdx.x;
    for (long i = t0; i < total; i += stride) {
        if (i < 6291456L)            dWi0[i]             = __float2half(Wi0[i]);
        else if (i < 10485760L)      dWh0[i - 6291456L]  = __float2half(Wh0[i - 6291456L]);
        else if (i < 14680064L)      dWi1[i - 10485760L] = __float2half(Wi1[i - 10485760L]);
        else                         dWh1[i - 14680064L] = __float2half(Wh1[i - 14680064L]);
    }
    if (t0 < 4 * H_) {
        dBs0[t0] = bi0[t0] + bh0[t0];
        dBs1[t0] = bi1[t0] + bh1[t0];
    }
}

__global__ void prep_emb(const int* __restrict__ tgt, const float* __restrict__ embW) {
    const long total = (long)S_ * B_ * E_;        // 4194304
    long stride = (long)gridDim.x * blockDim.x;
    long t0 = (long)blockIdx.x * blockDim.x + threadIdx.x;
    for (long i = t0; i < total; i += stride) {
        long sb = i >> 9;           // / E_
        int  e  = (int)(i & 511);
        int  tok = tgt[sb];
        dEmb[i] = __float2half(embW[(size_t)tok * E_ + e]);
    }
}

__global__ void prep_state(const float* __restrict__ h0, const float* __restrict__ c0,
                           const float* __restrict__ io) {
    int i = blockIdx.x * blockDim.x + threadIdx.x;
    if (i < B_ * H_) {
        dH0[0][i]  = __float2half(h0[i]);
        dH1[0][i]  = __float2half(h0[B_ * H_ + i]);
        dC0[i]     = c0[i];
        dC1[i]     = c0[B_ * H_ + i];
        dOut0[i]   = __float2half(io[i]);
    }
}

// ---------------------------------------------------------------------------
// Persistent main kernel helpers
// ---------------------------------------------------------------------------

#define CP_ASYNC16(dst, src) \
    asm volatile("cp.async.cg.shared.global [%0], [%1], 16;\n" :: "r"(dst), "l"(src))

// Resolve A (activation) / B (weight) base pointers + row strides for a k chunk.
__device__ __forceinline__ void get_ab(int layer, int t, int k0, int p,
                                       const __half*& ab, int& as_,
                                       const __half*& bb, int& bs_) {
    if (layer == 0) {
        if (k0 < E_)            { ab = dEmb + (size_t)t * B_ * E_ + k0;              as_ = E_; }
        else if (k0 < E_ + H_)  { ab = (t == 0 ? dOut0 : dH1[p]) + (k0 - E_);        as_ = H_; }
        else                    { ab = dH0[p] + (k0 - E_ - H_);                      as_ = H_; }
        if (k0 < E_ + H_)       { bb = dWi0 + k0;        bs_ = E_ + H_; }
        else                    { bb = dWh0 + (k0 - E_ - H_); bs_ = H_; }
    } else {
        int pn = p ^ 1;
        if (k0 < H_)            { ab = dH0[pn] + k0;        as_ = H_; bb = dWi1 + k0;        bs_ = H_; }
        else                    { ab = dH1[p] + (k0 - H_);  as_ = H_; bb = dWh1 + (k0 - H_); bs_ = H_; }
    }
}

__device__ __forceinline__ void load_chunk(int layer, int t, int k0, int p, int s, int blk,
                                           __half (*shA)[64][KP], __half (*shB)[NR][KP]) {
    const __half* ab; const __half* bb; int as_, bs_;
    get_ab(layer, t, k0, p, ab, as_, bb, bs_);
    const int tid = threadIdx.x;
    // A tile: 64 rows x 64 halves = 512 x 16B tasks
#pragma unroll
    for (int it = 0; it < 2; ++it) {
        int task = tid + it * NTH;
        int row = task >> 3, ch = task & 7;
        const __half* src = ab + (size_t)row * as_ + ch * 8;
        uint32_t dst = (uint32_t)__cvta_generic_to_shared(&shA[s][row][ch * 8]);
        CP_ASYNC16(dst, src);
    }
    // B tile: 32 rows x 64 halves = 256 x 16B tasks
    {
        int row = tid >> 3, ch = tid & 7;
        int wrow = (row >> 3) * H_ + blk * NJ + (row & 7);   // gate-major W row
        const __half* src = bb + (size_t)wrow * bs_ + ch * 8;
        uint32_t dst = (uint32_t)__cvta_generic_to_shared(&shB[s][row][ch * 8]);
        CP_ASYNC16(dst, src);
    }
    asm volatile("cp.async.commit_group;\n" ::: "memory");
}

__device__ __forceinline__ void mma_chunk(const __half (*sAp)[KP], const __half (*sBp)[KP],
                                          int m, int npair, int lane, float (*acc)[4]) {
#pragma unroll
    for (int sub = 0; sub < 4; ++sub) {
        const int kk  = sub * 16;
        const int grp = lane >> 3;
        const int arow = m + (lane & 7) + ((grp & 1) << 3);
        const int acol = kk + ((grp >> 1) << 3);
        uint32_t a0, a1, a2, a3;
        {
            uint32_t addr = (uint32_t)__cvta_generic_to_shared(&sAp[arow][acol]);
            asm volatile("ldmatrix.sync.aligned.m8n8.x4.shared.b16 {%0,%1,%2,%3}, [%4];\n"
                         : "=r"(a0), "=r"(a1), "=r"(a2), "=r"(a3) : "r"(addr));
        }
        const int brow = npair + (lane & 7) + (((lane >> 4) & 1) << 3);
        const int bcol = kk + (((lane >> 3) & 1) << 3);
        uint32_t b0, b1, b2, b3;
        {
            uint32_t addr = (uint32_t)__cvta_generic_to_shared(&sBp[brow][bcol]);
            asm volatile("ldmatrix.sync.aligned.m8n8.x4.shared.b16 {%0,%1,%2,%3}, [%4];\n"
                         : "=r"(b0), "=r"(b1), "=r"(b2), "=r"(b3) : "r"(addr));
        }
        asm volatile("mma.sync.aligned.m16n8k16.row.col.f32.f16.f16.f32 "
                     "{%0,%1,%2,%3},{%4,%5,%6,%7},{%8,%9},{%0,%1,%2,%3};\n"
                     : "+f"(acc[0][0]), "+f"(acc[0][1]), "+f"(acc[0][2]), "+f"(acc[0][3])
                     : "r"(a0), "r"(a1), "r"(a2), "r"(a3), "r"(b0), "r"(b1));
        asm volatile("mma.sync.aligned.m16n8k16.row.col.f32.f16.f16.f32 "
                     "{%0,%1,%2,%3},{%4,%5,%6,%7},{%8,%9},{%0,%1,%2,%3};\n"
                     : "+f"(acc[1][0]), "+f"(acc[1][1]), "+f"(acc[1][2]), "+f"(acc[1][3])
                     : "r"(a0), "r"(a1), "r"(a2), "r"(a3), "r"(b2), "r"(b3));
    }
}

__device__ __forceinline__ void grid_barrier(int target) {
    __syncthreads();
    if (threadIdx.x == 0) {
        __threadfence();
        atomicAdd(&g_count, 1);
        while (*((volatile int*)&g_count) < target) { }
        __threadfence();
    }
    __syncthreads();
}

// ---------------------------------------------------------------------------
// Persistent main kernel
// ---------------------------------------------------------------------------

__global__ void __launch_bounds__(NTH, 1) lstm_main(float* __restrict__ out) {
    __shared__ __align__(16) __half shA[2][64][KP];
    __shared__ __align__(16) __half shB[2][NR][KP];
    __shared__ float shG[64][NR + 1];

    const int tid  = threadIdx.x;
    const int blk  = blockIdx.x;
    const int lane = tid & 31;
    const int w    = tid >> 5;
    const int m     = (w & 3) << 4;   // m-tile base (batch rows)
    const int npair = (w >> 2) << 4;  // n-pair base (W rows within CTA tile)

    const size_t OFF_HN = (size_t)S_ * B_ * H_;
    const size_t OFF_CN = OFF_HN + 2 * (size_t)B_ * H_;

    int bar = 0;
    for (int t = 0; t < S_; ++t) {
        const int p  = t & 1;
        const int pn = p ^ 1;
        for (int layer = 0; layer < 2; ++layer) {
            const int K  = (layer == 0) ? (E_ + H_ + H_) : (H_ + H_);
            const int nc = K / KC;

            float acc[2][4];
#pragma unroll
            for (int i = 0; i < 2; ++i)
#pragma unroll
                for (int j = 0; j < 4; ++j) acc[i][j] = 0.f;

            load_chunk(layer, t, 0, p, 0, blk, shA, shB);
            for (int c = 0; c < nc; ++c) {
                if (c + 1 < nc) {
                    load_chunk(layer, t, (c + 1) * KC, p, (c + 1) & 1, blk, shA, shB);
                    asm volatile("cp.async.wait_group 1;\n" ::: "memory");
                } else {
                    asm volatile("cp.async.wait_group 0;\n" ::: "memory");
                }
                __syncthreads();
                mma_chunk(shA[c & 1], shB[c & 1], m, npair, lane, acc);
                __syncthreads();
            }

            // Epilogue: accumulators + bias -> shared gates buffer
            const float* bs = (layer == 0) ? dBs0 : dBs1;
#pragma unroll
            for (int nt = 0; nt < 2; ++nt) {
                int r0 = m + (lane >> 2);
                int cb = npair + nt * 8 + ((lane & 3) << 1);
#pragma unroll
                for (int e = 0; e < 2; ++e) {
                    int ncol = cb + e;
                    float bias = bs[(ncol >> 3) * H_ + blk * NJ + (ncol & 7)];
                    shG[r0][ncol]     = acc[nt][e]     + bias;
                    shG[r0 + 8][ncol] = acc[nt][2 + e] + bias;
                }
            }
            __syncthreads();

            // LSTM cell elementwise: 512 (b, j) pairs, 2 per thread
#pragma unroll
            for (int it = 0; it < 2; ++it) {
                int id = tid + it * NTH;
                int b  = id >> 3;
                int jj = id & 7;
                int jg = blk * NJ + jj;
                float gi = shG[b][jj];
                float gf = shG[b][8 + jj];
                float gg = shG[b][16 + jj];
                float go = shG[b][24 + jj];
                float si = 1.f / (1.f + __expf(-gi));
                float sf = 1.f / (1.f + __expf(-gf));
                float so = 1.f / (1.f + __expf(-go));
                float tg = tanhf(gg);
                int idx = b * H_ + jg;
                if (layer == 0) {
                    float cn = sf * dC0[idx] + si * tg;
                    dC0[idx] = cn;
                    float hn = so * tanhf(cn);
                    dH0[pn][idx] = __float2half(hn);
                    if (t == S_ - 1) {
                        out[OFF_HN + idx] = hn;
                        out[OFF_CN + idx] = cn;
                    }
                } else {
                    float cn = sf * dC1[idx] + si * tg;
                    dC1[idx] = cn;
                    float hn = so * tanhf(cn);
                    dH1[pn][idx] = __float2half(hn);
                    out[(size_t)t * B_ * H_ + idx] = hn;
                    if (t == S_ - 1) {
                        out[OFF_HN + B_ * H_ + idx] = hn;
                        out[OFF_CN + B_ * H_ + idx] = cn;
                    }
                }
            }

            // Grid-wide sync between phases; final phase: arrive + self-reset.
            if (t == S_ - 1 && layer == 1) {
                __syncthreads();
                if (tid == 0) {
                    __threadfence();
                    int old = atomicAdd(&g_count, 1);
                    if (old == 2 * S_ * GRID - 1) atomicExch(&g_count, 0);
                }
            } else {
                ++bar;
                grid_barrier(bar * GRID);
            }
        }
    }
}

// ---------------------------------------------------------------------------
// Launch
// ---------------------------------------------------------------------------

extern "C" void kernel_launch(void* const* d_in, const int* in_sizes, int n_in,
                              void* d_out, int out_size) {
    const int*   tgt  = (const int*)d_in[0];
    const float* h0   = (const float*)d_in[1];
    const float* c0   = (const float*)d_in[2];
    const float* io   = (const float*)d_in[3];
    const float* embW = (const float*)d_in[4];
    const float* Wi0  = (const float*)d_in[5];
    const float* Wh0  = (const float*)d_in[6];
    const float* bi0  = (const float*)d_in[7];
    const float* bh0  = (const float*)d_in[8];
    const float* Wi1  = (const float*)d_in[9];
    const float* Wh1  = (const float*)d_in[10];
    const float* bi1  = (const float*)d_in[11];
    const float* bh1  = (const float*)d_in[12];

    prep_weights<<<1024, 256>>>(Wi0, Wh0, Wi1, Wh1, bi0, bh0, bi1, bh1);
    prep_emb<<<2048, 256>>>(tgt, embW);
    prep_state<<<(B_ * H_ + 255) / 256, 256>>>(h0, c0, io);
    lstm_main<<<GRID, NTH>>>((float*)d_out);
}

// round 3
// speedup vs baseline: 1.8579x; 1.8579x over previous
#include <cuda_runtime.h>
#include <cuda_fp16.h>
#include <stdint.h>

// ---------------------------------------------------------------------------
// DecoderStackLSTM: persistent-kernel 2-layer input-feed LSTM decoder.
// S=128 steps, B=64 batch, E=512 emb, H=1024 hidden.
// One persistent kernel (128 CTAs), grid barrier between layer phases.
// R2/R3: all SMEM traffic via cp.async.bulk (2 bulk copies per K=512 chunk)
// into padded (stride-520-half) tiles; weights pre-reordered CTA-contiguous.
// ---------------------------------------------------------------------------

#define S_   128
#define B_   64
#define E_   512
#define H_   1024
#define NJ   8                  // hidden columns per CTA
#define NR   32                 // 4 gates * NJ weight rows per CTA
#define GRID 128
#define NTH  256
#define PW   520                // padded row width in halves (1040 B)
#define KCH  512                // K per chunk
#define ABYTES (64 * PW * 2)    // 66560
#define BBYTES (32 * PW * 2)    // 33280
#define CHBYTES (ABYTES + BBYTES)           // 99840
#define SMEM_G   (2 * CHBYTES)              // gates buffer offset 199680
#define SMEM_MB  (SMEM_G + 64 * 33 * 4)     // 208128
#define SMEM_TOT (SMEM_MB + 16)             // 208144

// Reordered weights: [blk][chunk][32 rows][520] contiguous per (blk,chunk)
static __device__ __align__(16) __half dW0[GRID * 5 * 32 * PW];
static __device__ __align__(16) __half dW1[GRID * 4 * 32 * PW];
// Embeddings per step: [S][64][520]
static __device__ __align__(16) __half dEmb[S_ * B_ * PW];
// States: [phase][colblock][64][520]
static __device__ __align__(16) __half dH0[2 * 2 * B_ * PW];
static __device__ __align__(16) __half dH1[2 * 2 * B_ * PW];
static __device__ __align__(16) __half dOutInit[2 * B_ * PW];
static __device__ float dC0[B_ * H_];
static __device__ float dC1[B_ * H_];
static __device__ float dBs0[4 * H_];
static __device__ float dBs1[4 * H_];
static __device__ int   g_count;    // zero-init; self-resets each run

// ---------------------------------------------------------------------------
// Prep kernels
// ---------------------------------------------------------------------------

__global__ void prep_weights(const float* __restrict__ Wi0, const float* __restrict__ Wh0,
                             const float* __restrict__ Wi1, const float* __restrict__ Wh1,
                             const float* __restrict__ bi0, const float* __restrict__ bh0,
                             const float* __restrict__ bi1, const float* __restrict__ bh1) {
    const long total0 = (long)GRID * 5 * 32 * 512;   // 10485760
    const long total1 = (long)GRID * 4 * 32 * 512;   //  8388608
    const long grand  = total0 + total1;
    long stride = (long)gridDim.x * blockDim.x;
    long t0 = (long)blockIdx.x * blockDim.x + threadIdx.x;
    for (long i = t0; i < grand; i += stride) {
        if (i < total0) {
            int blk = (int)(i / (5L * 32 * 512));
            int rem = (int)(i % (5L * 32 * 512));
            int c   = rem / (32 * 512);
            int r   = (rem >> 9) & 31;
            int col = rem & 511;
            int wrow = (r >> 3) * H_ + blk * NJ + (r & 7);
            int kk = c * 512 + col;
            float v = (kk < 1536) ? Wi0[(size_t)wrow * 1536 + kk]
                                  : Wh0[(size_t)wrow * 1024 + (kk - 1536)];
            dW0[(((size_t)blk * 5 + c) * 32 + r) * PW + col] = __float2half(v);
        } else {
            long j = i - total0;
            int blk = (int)(j / (4L * 32 * 512));
            int rem = (int)(j % (4L * 32 * 512));
            int c   = rem / (32 * 512);
            int r   = (rem >> 9) & 31;
            int col = rem & 511;
            int wrow = (r >> 3) * H_ + blk * NJ + (r & 7);
            int kk = c * 512 + col;
            float v = (kk < 1024) ? Wi1[(size_t)wrow * 1024 + kk]
                                  : Wh1[(size_t)wrow * 1024 + (kk - 1024)];
            dW1[(((size_t)blk * 4 + c) * 32 + r) * PW + col] = __float2half(v);
        }
    }
    if (t0 < 4 * H_) {
        dBs0[t0] = bi0[t0] + bh0[t0];
        dBs1[t0] = bi1[t0] + bh1[t0];
    }
}

__global__ void prep_emb(const int* __restrict__ tgt, const float* __restrict__ embW) {
    const long total = (long)S_ * B_ * E_;
    long stride = (long)gridDim.x * blockDim.x;
    long t0 = (long)blockIdx.x * blockDim.x + threadIdx.x;
    for (long i = t0; i < total; i += stride) {
        long sb = i >> 9;
        int  e  = (int)(i & 511);
        int  tok = tgt[sb];
        dEmb[sb * PW + e] = __float2half(embW[(size_t)tok * E_ + e]);
    }
}

__global__ void prep_state(const float* __restrict__ h0, const float* __restrict__ c0,
                           const float* __restrict__ io) {
    int i = blockIdx.x * blockDim.x + threadIdx.x;
    if (i < B_ * H_) {
        int b = i >> 10, j = i & 1023;
        int jb = j >> 9, col = j & 511;
        size_t p0 = ((size_t)(0 * 2 + jb) * B_ + b) * PW + col;
        dH0[p0]      = __float2half(h0[i]);
        dH1[p0]      = __float2half(h0[B_ * H_ + i]);
        dOutInit[((size_t)jb * B_ + b) * PW + col] = __float2half(io[i]);
        dC0[i] = c0[i];
        dC1[i] = c0[B_ * H_ + i];
    }
}

// ---------------------------------------------------------------------------
// PTX helpers
// ---------------------------------------------------------------------------

__device__ __forceinline__ void mbar_init(uint32_t a, int cnt) {
    asm volatile("mbarrier.init.shared.b64 [%0], %1;" :: "r"(a), "r"(cnt) : "memory");
}
__device__ __forceinline__ void mbar_expect_tx(uint32_t a, uint32_t bytes) {
    asm volatile("mbarrier.arrive.expect_tx.shared.b64 _, [%0], %1;" :: "r"(a), "r"(bytes) : "memory");
}
__device__ __forceinline__ void bulk_g2s(uint32_t dst, const void* src, uint32_t bytes, uint32_t mbar) {
    asm volatile("cp.async.bulk.shared::cluster.global.mbarrier::complete_tx::bytes "
                 "[%0], [%1], %2, [%3];"
                 :: "r"(dst), "l"(src), "r"(bytes), "r"(mbar) : "memory");
}
__device__ __forceinline__ void mbar_wait(uint32_t a, int parity) {
    asm volatile(
        "{\n\t.reg .pred P;\n"
        "W%=:\n\tmbarrier.try_wait.parity.shared::cta.b64 P, [%0], %1;\n"
        "\t@P bra D%=;\n"
        "\tbra W%=;\n"
        "D%=:\n\t}"
        :: "r"(a), "r"(parity) : "memory");
}

// A-chunk source pointer for (layer, chunk, t, phase)
__device__ __forceinline__ const __half* a_src(int layer, int c, int t, int p) {
    if (layer == 0) {
        if (c == 0) return dEmb + (size_t)t * B_ * PW;
        if (c <= 2) {
            int jb = c - 1;
            return (t == 0) ? dOutInit + (size_t)jb * B_ * PW
                            : dH1 + ((size_t)(p * 2 + jb) * B_) * PW;
        }
        int jb = c - 3;
        return dH0 + ((size_t)(p * 2 + jb) * B_) * PW;
    } else {
        int pn = p ^ 1;
        if (c < 2) return dH0 + ((size_t)(pn * 2 + c) * B_) * PW;
        return dH1 + ((size_t)(p * 2 + (c - 2)) * B_) * PW;
    }
}

__device__ __forceinline__ void issue_chunk(int layer, int c, int t, int p, int stage,
                                            int blk, uint32_t smem_base, uint32_t mbar) {
    const __half* as = a_src(layer, c, t, p);
    const __half* bs = (layer == 0) ? dW0 + ((size_t)blk * 5 + c) * 32 * PW
                                    : dW1 + ((size_t)blk * 4 + c) * 32 * PW;
    uint32_t adst = smem_base + stage * CHBYTES;
    mbar_expect_tx(mbar, CHBYTES);
    bulk_g2s(adst, as, ABYTES, mbar);
    bulk_g2s(adst + ABYTES, bs, BBYTES, mbar);
}

__device__ __forceinline__ void mma_chunk(const __half* sA, const __half* sB,
                                          int m, int npair, int lane, float (*acc)[4]) {
#pragma unroll
    for (int sub = 0; sub < 32; ++sub) {
        const int kk  = sub * 16;
        const int grp = lane >> 3;
        const int arow = m + (lane & 7) + ((grp & 1) << 3);
        const int acol = kk + ((grp >> 1) << 3);
        uint32_t a0, a1, a2, a3;
        {
            uint32_t addr = (uint32_t)__cvta_generic_to_shared(sA + arow * PW + acol);
            asm volatile("ldmatrix.sync.aligned.m8n8.x4.shared.b16 {%0,%1,%2,%3}, [%4];\n"
                         : "=r"(a0), "=r"(a1), "=r"(a2), "=r"(a3) : "r"(addr));
        }
        const int brow = npair + (lane & 7) + (((lane >> 4) & 1) << 3);
        const int bcol = kk + (((lane >> 3) & 1) << 3);
        uint32_t b0, b1, b2, b3;
        {
            uint32_t addr = (uint32_t)__cvta_generic_to_shared(sB + brow * PW + bcol);
            asm volatile("ldmatrix.sync.aligned.m8n8.x4.shared.b16 {%0,%1,%2,%3}, [%4];\n"
                         : "=r"(b0), "=r"(b1), "=r"(b2), "=r"(b3) : "r"(addr));
        }
        asm volatile("mma.sync.aligned.m16n8k16.row.col.f32.f16.f16.f32 "
                     "{%0,%1,%2,%3},{%4,%5,%6,%7},{%8,%9},{%0,%1,%2,%3};\n"
                     : "+f"(acc[0][0]), "+f"(acc[0][1]), "+f"(acc[0][2]), "+f"(acc[0][3])
                     : "r"(a0), "r"(a1), "r"(a2), "r"(a3), "r"(b0), "r"(b1));
        asm volatile("mma.sync.aligned.m16n8k16.row.col.f32.f16.f16.f32 "
                     "{%0,%1,%2,%3},{%4,%5,%6,%7},{%8,%9},{%0,%1,%2,%3};\n"
                     : "+f"(acc[1][0]), "+f"(acc[1][1]), "+f"(acc[1][2]), "+f"(acc[1][3])
                     : "r"(a0), "r"(a1), "r"(a2), "r"(a3), "r"(b2), "r"(b3));
    }
}

__device__ __forceinline__ void grid_barrier(int target) {
    __syncthreads();
    if (threadIdx.x == 0) {
        __threadfence();
        atomicAdd(&g_count, 1);
        while (*((volatile int*)&g_count) < target) { }
        __threadfence();
    }
    __syncthreads();
}

// ---------------------------------------------------------------------------
// Persistent main kernel
// ---------------------------------------------------------------------------

extern __shared__ __align__(128) unsigned char smem_raw[];

__global__ void __launch_bounds__(NTH, 1) lstm_main(float* __restrict__ out) {
    const int tid  = threadIdx.x;
    const int blk  = blockIdx.x;
    const int lane = tid & 31;
    const int w    = tid >> 5;
    const int m     = (w & 3) << 4;    // batch-row tile base
    const int npair = (w >> 2) << 4;   // weight-row tile base within NR

    uint32_t smem_base = (uint32_t)__cvta_generic_to_shared(smem_raw);
    float*   shG       = (float*)(smem_raw + SMEM_G);      // [64][33]
    uint32_t mb[2]     = { smem_base + SMEM_MB, smem_base + SMEM_MB + 8 };

    if (tid == 0) { mbar_init(mb[0], 1); mbar_init(mb[1], 1); }
    __syncthreads();
    int ph[2] = {0, 0};

    const size_t OFF_HN = (size_t)S_ * B_ * H_;
    const size_t OFF_CN = OFF_HN + 2 * (size_t)B_ * H_;

    int bar = 0;
    for (int t = 0; t < S_; ++t) {
        const int p  = t & 1;
        const int pn = p ^ 1;
        for (int layer = 0; layer < 2; ++layer) {
            const int nc = (layer == 0) ? 5 : 4;

            float acc[2][4];
#pragma unroll
            for (int i = 0; i < 2; ++i)
#pragma unroll
                for (int j = 0; j < 4; ++j) acc[i][j] = 0.f;

            if (tid == 0) issue_chunk(layer, 0, t, p, 0, blk, smem_base, mb[0]);
            for (int c = 0; c < nc; ++c) {
                int s = c & 1;
                if (c + 1 < nc && tid == 0)
                    issue_chunk(layer, c + 1, t, p, (c + 1) & 1, blk, smem_base, mb[(c + 1) & 1]);
                mbar_wait(mb[s], ph[s]);
                ph[s] ^= 1;
                const __half* sA = (const __half*)(smem_raw + s * CHBYTES);
                const __half* sB = sA + 64 * PW;
                mma_chunk(sA, sB, m, npair, lane, acc);
                __syncthreads();
            }

            // Epilogue: accumulators + bias -> shared gates buffer
            const float* bs = (layer == 0) ? dBs0 : dBs1;
#pragma unroll
            for (int nt = 0; nt < 2; ++nt) {
                int r0 = m + (lane >> 2);
                int cb = npair + nt * 8 + ((lane & 3) << 1);
#pragma unroll
                for (int e = 0; e < 2; ++e) {
                    int ncol = cb + e;
                    float bias = bs[(ncol >> 3) * H_ + blk * NJ + (ncol & 7)];
                    shG[r0 * 33 + ncol]       = acc[nt][e]     + bias;
                    shG[(r0 + 8) * 33 + ncol] = acc[nt][2 + e] + bias;
                }
            }
            __syncthreads();

            // LSTM cell elementwise: 512 (b, j) pairs, 2 per thread
#pragma unroll
            for (int it = 0; it < 2; ++it) {
                int id = tid + it * NTH;
                int b  = id >> 3;
                int jj = id & 7;
                int jg = blk * NJ + jj;
                float gi = shG[b * 33 + jj];
                float gf = shG[b * 33 + 8 + jj];
                float gg = shG[b * 33 + 16 + jj];
                float go = shG[b * 33 + 24 + jj];
                float si = 1.f / (1.f + __expf(-gi));
                float sf = 1.f / (1.f + __expf(-gf));
                float so = 1.f / (1.f + __expf(-go));
                float tg = tanhf(gg);
                int idx = b * H_ + jg;
                int jb  = jg >> 9;
                int col = jg & 511;
                size_t hidx = ((size_t)(pn * 2 + jb) * B_ + b) * PW + col;
                if (layer == 0) {
                    float cn = sf * dC0[idx] + si * tg;
                    dC0[idx] = cn;
                    float hn = so * tanhf(cn);
                    dH0[hidx] = __float2half(hn);
                    if (t == S_ - 1) {
                        out[OFF_HN + idx] = hn;
                        out[OFF_CN + idx] = cn;
                    }
                } else {
                    float cn = sf * dC1[idx] + si * tg;
                    dC1[idx] = cn;
                    float hn = so * tanhf(cn);
                    dH1[hidx] = __float2half(hn);
                    out[(size_t)t * B_ * H_ + idx] = hn;
                    if (t == S_ - 1) {
                        out[OFF_HN + B_ * H_ + idx] = hn;
                        out[OFF_CN + B_ * H_ + idx] = cn;
                    }
                }
            }

            // Grid-wide sync between phases; final phase: arrive + self-reset.
            if (t == S_ - 1 && layer == 1) {
                __syncthreads();
                if (tid == 0) {
                    __threadfence();
                    int old = atomicAdd(&g_count, 1);
                    if (old == 2 * S_ * GRID - 1) atomicExch(&g_count, 0);
                }
            } else {
                ++bar;
                grid_barrier(bar * GRID);
            }
        }
    }
}

// ---------------------------------------------------------------------------
// Launch
// ---------------------------------------------------------------------------

extern "C" void kernel_launch(void* const* d_in, const int* in_sizes, int n_in,
                              void* d_out, int out_size) {
    const int*   tgt  = (const int*)d_in[0];
    const float* h0   = (const float*)d_in[1];
    const float* c0   = (const float*)d_in[2];
    const float* io   = (const float*)d_in[3];
    const float* embW = (const float*)d_in[4];
    const float* Wi0  = (const float*)d_in[5];
    const float* Wh0  = (const float*)d_in[6];
    const float* bi0  = (const float*)d_in[7];
    const float* bh0  = (const float*)d_in[8];
    const float* Wi1  = (const float*)d_in[9];
    const float* Wh1  = (const float*)d_in[10];
    const float* bi1  = (const float*)d_in[11];
    const float* bh1  = (const float*)d_in[12];

    cudaFuncSetAttribute(lstm_main, cudaFuncAttributeMaxDynamicSharedMemorySize, SMEM_TOT);

    prep_weights<<<1024, 256>>>(Wi0, Wh0, Wi1, Wh1, bi0, bh0, bi1, bh1);
    prep_emb<<<2048, 256>>>(tgt, embW);
    prep_state<<<(B_ * H_ + 255) / 256, 256>>>(h0, c0, io);
    lstm_main<<<GRID, NTH, SMEM_TOT>>>((float*)d_out);
}